// round 2
// baseline (speedup 1.0000x reference)
#include <cuda_runtime.h>
#include <cstdint>
#include <math.h>

// Problem constants
constexpr int BB = 1024;
constexpr int TT = 120;
constexpr int EE = 50;
constexpr int HH = 300;
constexpr int CC = 5;
constexpr int KTOT = EE + HH;       // 350
constexpr int Z4H = 4 * HH;         // 1200

// Step-kernel tiling
constexpr int TM = 64;              // rows per block
constexpr int RB = BB / TM;         // 16 row blocks
constexpr int POS = 17;             // gate positions per block
constexpr int PB = 18;              // 18*17 = 306 >= 300
constexpr int NT = 136;             // 8*17 threads
constexpr int KC = 32;              // K chunk
constexpr int NCHUNK = 11;          // 11*32 = 352 >= 350 (zero padded)

// CE kernel
constexpr int TOKENS = BB * TT;         // 122880
constexpr int CE_WARPS = 8;
constexpr int CE_BLOCKS = TOKENS / CE_WARPS;  // 15360
constexpr int RED_BLOCKS = 64;
constexpr int RED_PER = CE_BLOCKS / RED_BLOCKS; // 240

// ----------------- device scratch (no cudaMalloc allowed) -----------------
__device__ float  g_x[BB * TT * EE];       // gathered embeddings  (24.6 MB)
__device__ float  g_hs[BB * TT * HH];      // all hidden states    (147 MB)
__device__ float  g_h[2][BB * HH];         // double-buffered h
__device__ float  g_c[BB * HH];            // cell state
__device__ double g_bsum[CE_BLOCKS];
__device__ int    g_bcnt[CE_BLOCKS];
__device__ double g_rsum[RED_BLOCKS];
__device__ int    g_rcnt[RED_BLOCKS];
__device__ int    g_mask_is_byte;

// ----------------- helpers -----------------
__device__ __forceinline__ void fma2(unsigned long long& d,
                                     unsigned long long a,
                                     unsigned long long b) {
    asm("fma.rn.f32x2 %0, %1, %2, %0;" : "+l"(d) : "l"(a), "l"(b));
}

__device__ __forceinline__ float2 unpack2(unsigned long long u) {
    float2 r;
    r.x = __int_as_float((int)(u & 0xffffffffULL));
    r.y = __int_as_float((int)(u >> 32));
    return r;
}

__device__ __forceinline__ float sigf(float x) {
    return 1.0f / (1.0f + expf(-x));
}

// ----------------- kernels -----------------

__global__ void init_k() {
    int idx = blockIdx.x * blockDim.x + threadIdx.x;
    if (idx < BB * HH) {
        g_h[0][idx] = 0.f;
        g_h[1][idx] = 0.f;
        g_c[idx] = 0.f;
    }
    if (idx == 0) g_mask_is_byte = 0;
}

// mask dtype detection: scan first 122880 bytes as u32 words; any word > 1
// means the buffer is byte-bools (int32 0/1 words are always <= 1).
__global__ void detect_k(const unsigned int* __restrict__ mw) {
    int idx = blockIdx.x * blockDim.x + threadIdx.x;
    if (idx < TOKENS / 4) {
        if (mw[idx] > 1u) g_mask_is_byte = 1;  // benign race, same value
    }
}

__global__ void gather_k(const int* __restrict__ tokens,
                         const float* __restrict__ emb) {
    int idx = blockIdx.x * blockDim.x + threadIdx.x;
    if (idx < BB * TT * EE) {
        int e = idx % EE;
        int bt = idx / EE;
        int tok = tokens[bt];
        g_x[idx] = emb[tok * EE + e];
    }
}

// One LSTM time step: z = [x_t|h_prev] @ [Wx;Wh] + b, gates, update c/h.
// grid (16, 18), 136 threads. Thread (tx,ty): position p0+tx, rows ty*8..+7.
__global__ __launch_bounds__(NT) void lstm_step_k(
    int t,
    const float* __restrict__ Wx, const float* __restrict__ Wh,
    const float* __restrict__ bias)
{
    const float* __restrict__ hprev = g_h[t & 1];
    float* __restrict__ hnext = g_h[(t + 1) & 1];

    __shared__ __align__(16) float As[KC][68];        // [k][row], padded
    __shared__ __align__(16) float Ws[KC][POS][4][2]; // [k][pos][gate][dup]

    const int tid = threadIdx.x;
    const int tx = tid % POS;       // position lane (0..16)
    const int ty = tid / POS;       // row group   (0..7)
    const int b0 = blockIdx.x * TM;
    const int p0 = blockIdx.y * POS;

    unsigned long long acc[4][4];   // [rowpair][gate]
#pragma unroll
    for (int i = 0; i < 4; ++i)
#pragma unroll
        for (int g = 0; g < 4; ++g) acc[i][g] = 0ull;

    for (int chunk = 0; chunk < NCHUNK; ++chunk) {
        const int k0 = chunk * KC;

        // Load A tile (x_t columns then h columns), zero-padded past K=350.
        for (int i = tid; i < KC * TM; i += NT) {
            int kc = i & 31, r = i >> 5;
            int k = k0 + kc;
            int b = b0 + r;
            float v = 0.f;
            if (k < EE)        v = g_x[(b * TT + t) * EE + k];
            else if (k < KTOT) v = hprev[b * HH + (k - EE)];
            As[kc][r] = v;
        }
        // Load W tile, duplicated for f32x2; zero-pad invalid pos/k.
        {
            const int q0 = ty;
#pragma unroll
            for (int it = 0; it < 16; ++it) {
                int q = q0 + it * 8;       // 0..127
                int g = q & 3, kc = q >> 2;
                int k = k0 + kc;
                int pg = p0 + tx;
                float v = 0.f;
                if (pg < HH && k < KTOT) {
                    int col = g * HH + pg;
                    v = (k < EE) ? Wx[k * Z4H + col] : Wh[(k - EE) * Z4H + col];
                }
                Ws[kc][tx][g][0] = v;
                Ws[kc][tx][g][1] = v;
            }
        }
        __syncthreads();

        const unsigned long long* asp =
            reinterpret_cast<const unsigned long long*>(&As[0][ty * 8]);
        const unsigned long long* wsp =
            reinterpret_cast<const unsigned long long*>(&Ws[0][tx][0][0]);

#pragma unroll
        for (int kc = 0; kc < KC; ++kc) {
            unsigned long long a0 = asp[kc * 34 + 0];
            unsigned long long a1 = asp[kc * 34 + 1];
            unsigned long long a2 = asp[kc * 34 + 2];
            unsigned long long a3 = asp[kc * 34 + 3];
            unsigned long long w0 = wsp[kc * 68 + 0];
            unsigned long long w1 = wsp[kc * 68 + 1];
            unsigned long long w2 = wsp[kc * 68 + 2];
            unsigned long long w3 = wsp[kc * 68 + 3];
            fma2(acc[0][0], a0, w0); fma2(acc[0][1], a0, w1);
            fma2(acc[0][2], a0, w2); fma2(acc[0][3], a0, w3);
            fma2(acc[1][0], a1, w0); fma2(acc[1][1], a1, w1);
            fma2(acc[1][2], a1, w2); fma2(acc[1][3], a1, w3);
            fma2(acc[2][0], a2, w0); fma2(acc[2][1], a2, w1);
            fma2(acc[2][2], a2, w2); fma2(acc[2][3], a2, w3);
            fma2(acc[3][0], a3, w0); fma2(acc[3][1], a3, w1);
            fma2(acc[3][2], a3, w2); fma2(acc[3][3], a3, w3);
        }
        __syncthreads();
    }

    // Epilogue: gates + state update + hs store.
    const int p = p0 + tx;
    if (p < HH) {
        const float bi = bias[p];
        const float bj = bias[HH + p];
        const float bf = bias[2 * HH + p];
        const float bo = bias[3 * HH + p];
#pragma unroll
        for (int pr = 0; pr < 4; ++pr) {
            float2 vi = unpack2(acc[pr][0]);
            float2 vj = unpack2(acc[pr][1]);
            float2 vf = unpack2(acc[pr][2]);
            float2 vo = unpack2(acc[pr][3]);
            int r0 = ty * 8 + pr * 2;
            {
                int b = b0 + r0;
                int ci = b * HH + p;
                float iv = vi.x + bi, jv = vj.x + bj;
                float fv = vf.x + bf, ov = vo.x + bo;
                float cold = g_c[ci];
                float cn = sigf(fv + 1.0f) * cold + sigf(iv) * tanhf(jv);
                float hn = sigf(ov) * tanhf(cn);
                g_c[ci] = cn;
                hnext[ci] = hn;
                g_hs[(b * TT + t) * HH + p] = hn;
            }
            {
                int b = b0 + r0 + 1;
                int ci = b * HH + p;
                float iv = vi.y + bi, jv = vj.y + bj;
                float fv = vf.y + bf, ov = vo.y + bo;
                float cold = g_c[ci];
                float cn = sigf(fv + 1.0f) * cold + sigf(iv) * tanhf(jv);
                float hn = sigf(ov) * tanhf(cn);
                g_c[ci] = cn;
                hnext[ci] = hn;
                g_hs[(b * TT + t) * HH + p] = hn;
            }
        }
    }
}

// Output projection + log-softmax + CE. One warp per token, 8 warps/block.
__global__ void ce_k(const float* __restrict__ U, const float* __restrict__ b2,
                     const int* __restrict__ labels, const void* __restrict__ maskp)
{
    __shared__ double ssum[CE_WARPS];
    __shared__ int    scnt[CE_WARPS];

    int warp = threadIdx.x >> 5;
    int lane = threadIdx.x & 31;
    int tok = blockIdx.x * CE_WARPS + warp;

    const float* hrow = g_hs + (size_t)tok * HH;
    float s0 = 0.f, s1 = 0.f, s2 = 0.f, s3 = 0.f, s4 = 0.f;
    for (int k = lane; k < HH; k += 32) {
        float hv = hrow[k];
        const float* ur = U + k * CC;
        s0 += hv * ur[0]; s1 += hv * ur[1]; s2 += hv * ur[2];
        s3 += hv * ur[3]; s4 += hv * ur[4];
    }
#pragma unroll
    for (int off = 16; off; off >>= 1) {
        s0 += __shfl_down_sync(0xffffffffu, s0, off);
        s1 += __shfl_down_sync(0xffffffffu, s1, off);
        s2 += __shfl_down_sync(0xffffffffu, s2, off);
        s3 += __shfl_down_sync(0xffffffffu, s3, off);
        s4 += __shfl_down_sync(0xffffffffu, s4, off);
    }
    if (lane == 0) {
        s0 += b2[0]; s1 += b2[1]; s2 += b2[2]; s3 += b2[3]; s4 += b2[4];
        float m = fmaxf(fmaxf(fmaxf(s0, s1), fmaxf(s2, s3)), s4);
        float sum = expf(s0 - m) + expf(s1 - m) + expf(s2 - m)
                  + expf(s3 - m) + expf(s4 - m);
        float lse = m + logf(sum);
        int lab = labels[tok];
        float lc = (lab == 0) ? s0 : (lab == 1) ? s1 : (lab == 2) ? s2
                 : (lab == 3) ? s3 : s4;
        float ce = lse - lc;
        int mk;
        if (g_mask_is_byte) mk = (((const unsigned char*)maskp)[tok] != 0);
        else                mk = (((const int*)maskp)[tok] != 0);
        ssum[warp] = mk ? (double)ce : 0.0;
        scnt[warp] = mk;
    }
    __syncthreads();
    if (threadIdx.x == 0) {
        double s = 0.0; int c = 0;
        for (int w = 0; w < CE_WARPS; ++w) { s += ssum[w]; c += scnt[w]; }
        g_bsum[blockIdx.x] = s;
        g_bcnt[blockIdx.x] = c;
    }
}

// Deterministic fixed-order reduction of the 15360 block partials.
__global__ void red_k() {
    __shared__ double sd[256];
    __shared__ int    sc[256];
    int j = blockIdx.x;
    int i = threadIdx.x;
    double s = 0.0; int c = 0;
    if (i < RED_PER) {
        s = g_bsum[j * RED_PER + i];
        c = g_bcnt[j * RED_PER + i];
    }
    sd[i] = s; sc[i] = c;
    __syncthreads();
    for (int off = 128; off; off >>= 1) {
        if (i < off) { sd[i] += sd[i + off]; sc[i] += sc[i + off]; }
        __syncthreads();
    }
    if (i == 0) { g_rsum[j] = sd[0]; g_rcnt[j] = sc[0]; }
}

__global__ void fin_k(float* out) {
    if (threadIdx.x == 0 && blockIdx.x == 0) {
        double s = 0.0; int c = 0;
        for (int j = 0; j < RED_BLOCKS; ++j) { s += g_rsum[j]; c += g_rcnt[j]; }
        out[0] = (float)(s / (double)c);
    }
}

// ----------------- launcher -----------------
extern "C" void kernel_launch(void* const* d_in, const int* in_sizes, int n_in,
                              void* d_out, int out_size)
{
    const int*   tokens = (const int*)d_in[0];
    const int*   labels = (const int*)d_in[1];
    const void*  mask   = d_in[2];                 // bool (byte or i32, detected)
    const float* emb    = (const float*)d_in[3];
    const float* Wx     = (const float*)d_in[4];
    const float* Wh     = (const float*)d_in[5];
    const float* bias   = (const float*)d_in[6];
    const float* U      = (const float*)d_in[7];
    const float* b2     = (const float*)d_in[8];
    float* out = (float*)d_out;

    init_k<<<(BB * HH + 255) / 256, 256>>>();
    detect_k<<<(TOKENS / 4 + 255) / 256, 256>>>((const unsigned int*)mask);
    gather_k<<<(BB * TT * EE + 255) / 256, 256>>>(tokens, emb);

    dim3 sgrid(RB, PB);
    for (int t = 0; t < TT; ++t) {
        lstm_step_k<<<sgrid, NT>>>(t, Wx, Wh, bias);
    }

    ce_k<<<CE_BLOCKS, CE_WARPS * 32>>>(U, b2, labels, mask);
    red_k<<<RED_BLOCKS, 256>>>();
    fin_k<<<1, 32>>>(out);
    (void)in_sizes; (void)n_in; (void)out_size;
}

// round 4
// speedup vs baseline: 1.0402x; 1.0402x over previous
#include <cuda_runtime.h>
#include <cstdint>
#include <math.h>

// Problem constants
constexpr int BB = 1024;
constexpr int TT = 120;
constexpr int EE = 50;
constexpr int HH = 300;
constexpr int CC = 5;
constexpr int KTOT = EE + HH;        // 350
constexpr int KPAD = 352;            // 11 * 32
constexpr int NZ = 4 * HH;           // 1200
constexpr int NZP = 1224;            // 17 * 72 padded cols

// GEMM tiling: grid (8 row-blocks x 17 col-blocks) = 136 blocks, 256 threads
constexpr int GM = 128;              // rows per block
constexpr int GN = 72;               // cols per block
constexpr int KC = 32;               // K chunk
constexpr int NCHUNK = KPAD / KC;    // 11

// CE kernel
constexpr int TOKENS = BB * TT;                 // 122880
constexpr int CE_WARPS = 8;
constexpr int CE_BLOCKS = TOKENS / CE_WARPS;    // 15360
constexpr int RED_BLOCKS = 64;
constexpr int RED_PER = CE_BLOCKS / RED_BLOCKS; // 240

// ----------------- device scratch (no cudaMalloc allowed) -----------------
__device__ float  g_xT[TT * EE * BB];      // x transposed  [t][e][b]   24.6 MB
__device__ float  g_W[KPAD * NZP];         // padded [Wx;Wh]            1.72 MB
__device__ float  g_hT[2][HH * BB];        // h transposed  [h][b], x2
__device__ float  g_c[BB * HH];            // cell state    [b][p]
__device__ float  g_z[BB * NZP];           // pre-activation z          5.0 MB
__device__ float  g_hs[BB * TT * HH];      // hidden states [b][t][p]   147 MB
__device__ double g_bsum[CE_BLOCKS];
__device__ int    g_bcnt[CE_BLOCKS];
__device__ double g_rsum[RED_BLOCKS];
__device__ int    g_rcnt[RED_BLOCKS];
__device__ int    g_mask_is_byte;

// ----------------- helpers -----------------
__device__ __forceinline__ void fma2(unsigned long long& d,
                                     unsigned long long a,
                                     unsigned long long b) {
    asm("fma.rn.f32x2 %0, %1, %2, %0;" : "+l"(d) : "l"(a), "l"(b));
}

__device__ __forceinline__ float2 unpack2(unsigned long long u) {
    float2 r;
    r.x = __int_as_float((int)(u & 0xffffffffULL));
    r.y = __int_as_float((int)(u >> 32));
    return r;
}

__device__ __forceinline__ float sigf(float x) {
    return 1.0f / (1.0f + expf(-x));
}

// ----------------- setup kernels -----------------

__global__ void init_k() {
    int idx = blockIdx.x * blockDim.x + threadIdx.x;
    if (idx < HH * BB) {
        g_hT[0][idx] = 0.f;
        g_hT[1][idx] = 0.f;
    }
    if (idx < BB * HH) g_c[idx] = 0.f;
    if (idx == 0) g_mask_is_byte = 0;
}

// mask dtype detection: any u32 word > 1 => byte-bool storage.
__global__ void detect_k(const unsigned int* __restrict__ mw) {
    int idx = blockIdx.x * blockDim.x + threadIdx.x;
    if (idx < TOKENS / 4) {
        if (mw[idx] > 1u) g_mask_is_byte = 1;  // benign race, same value
    }
}

// Build padded weight matrix g_W[k][c]: rows 0..49 = Wx, 50..349 = Wh, rest 0.
__global__ void wpad_k(const float* __restrict__ Wx,
                       const float* __restrict__ Wh) {
    int idx = blockIdx.x * blockDim.x + threadIdx.x;
    if (idx < KPAD * NZP) {
        int k = idx / NZP, c = idx % NZP;
        float v = 0.f;
        if (c < NZ) {
            if (k < EE)        v = Wx[k * NZ + c];
            else if (k < KTOT) v = Wh[(k - EE) * NZ + c];
        }
        g_W[idx] = v;
    }
}

// Gather embeddings transposed: g_xT[t][e][b] = emb[tokens[b][t]][e].
__global__ void gather_k(const int* __restrict__ tokens,
                         const float* __restrict__ emb) {
    int idx = blockIdx.x * blockDim.x + threadIdx.x;
    if (idx < TT * EE * BB) {
        int b = idx % BB;
        int te = idx / BB;
        int e = te % EE;
        int t = te / EE;
        int tok = tokens[b * TT + t];
        g_xT[idx] = emb[tok * EE + e];
    }
}

// ----------------- per-step GEMM: z = [x_t | h_prev] @ Wpad -----------------
// grid (8, 17), 256 threads. Thread (ty=tid/8, tx=tid%8):
//   rows r0 + ty*4 .. +3 (as 2 f32x2 pairs), cols c0 + tx + 8j, j=0..8.
__global__ __launch_bounds__(256) void lstm_gemm_k(int t) {
    __shared__ __align__(16) float As[KC][GM];        // [kc][row]
    __shared__ __align__(16) float Ws[KC][GN][2];     // [kc][col][dup]

    const int tid = threadIdx.x;
    const int tx = tid & 7;
    const int ty = tid >> 3;           // 0..31
    const int r0 = blockIdx.x * GM;
    const int c0 = blockIdx.y * GN;
    const float* __restrict__ hT = g_hT[t & 1];

    unsigned long long acc[2][9];
#pragma unroll
    for (int p = 0; p < 2; ++p)
#pragma unroll
        for (int j = 0; j < 9; ++j) acc[p][j] = 0ull;

    for (int chunk = 0; chunk < NCHUNK; ++chunk) {
        const int k0 = chunk * KC;

        // A tile: As[kc][r] <- (k<50 ? xT[t][k][r0+r] : k<350 ? hT[k-50][r0+r] : 0)
        // i = tid + n*256: r = tid & 127 (coalesced), kc = 2n + tid/128.
        {
            const int r = tid & 127;
            const int kbase = k0 + (tid >> 7);     // +0 or +1
#pragma unroll
            for (int n = 0; n < 16; ++n) {
                int kc = (n << 1) + (tid >> 7);
                int k = kbase + (n << 1);
                float v = 0.f;
                if (k < EE)        v = g_xT[(t * EE + k) * BB + r0 + r];
                else if (k < KTOT) v = hT[(k - EE) * BB + r0 + r];
                As[kc][r] = v;
            }
        }
        // W tile, duplicated for f32x2: Ws[kc][j][0..1] = Wpad[k0+kc][c0+j]
        {
#pragma unroll
            for (int n = 0; n < 9; ++n) {
                int i = tid + n * 256;            // 0..2303
                int j = i % GN;
                int kc = i / GN;
                float v = g_W[(k0 + kc) * NZP + c0 + j];
                Ws[kc][j][0] = v;
                Ws[kc][j][1] = v;
            }
        }
        __syncthreads();

        const int ty4 = ty * 4;
#pragma unroll
        for (int kc = 0; kc < KC; ++kc) {
            unsigned long long a0 =
                *reinterpret_cast<const unsigned long long*>(&As[kc][ty4]);
            unsigned long long a1 =
                *reinterpret_cast<const unsigned long long*>(&As[kc][ty4 + 2]);
#pragma unroll
            for (int j = 0; j < 9; ++j) {
                unsigned long long w =
                    *reinterpret_cast<const unsigned long long*>(&Ws[kc][tx + 8 * j][0]);
                fma2(acc[0][j], a0, w);
                fma2(acc[1][j], a1, w);
            }
        }
        __syncthreads();
    }

    // Write z tile (cols >= 1200 are dead but harmless; W there is zero).
#pragma unroll
    for (int p = 0; p < 2; ++p) {
#pragma unroll
        for (int j = 0; j < 9; ++j) {
            float2 v = unpack2(acc[p][j]);
            int row = r0 + ty * 4 + p * 2;
            int col = c0 + tx + 8 * j;
            g_z[row * NZP + col] = v.x;
            g_z[(row + 1) * NZP + col] = v.y;
        }
    }
}

// ----------------- per-step gate/update kernel -----------------
// idx -> (b = idx/300, p = idx%300); all loads/stores p-contiguous except hT.
__global__ void gate_k(int t, const float* __restrict__ bias) {
    int idx = blockIdx.x * blockDim.x + threadIdx.x;  // < 307200
    int p = idx % HH;
    int b = idx / HH;
    const float* zr = g_z + b * NZP;
    float iv = zr[p]            + bias[p];
    float jv = zr[HH + p]       + bias[HH + p];
    float fv = zr[2 * HH + p]   + bias[2 * HH + p];
    float ov = zr[3 * HH + p]   + bias[3 * HH + p];
    float cold = g_c[idx];
    float cn = sigf(fv + 1.0f) * cold + sigf(iv) * tanhf(jv);
    float hn = sigf(ov) * tanhf(cn);
    g_c[idx] = cn;
    g_hs[(b * TT + t) * HH + p] = hn;
    g_hT[(t + 1) & 1][p * BB + b] = hn;
}

// ----------------- CE: projection + log-softmax + masked sum -----------------
__global__ void ce_k(const float* __restrict__ U, const float* __restrict__ b2,
                     const int* __restrict__ labels, const void* __restrict__ maskp)
{
    __shared__ double ssum[CE_WARPS];
    __shared__ int    scnt[CE_WARPS];

    int warp = threadIdx.x >> 5;
    int lane = threadIdx.x & 31;
    int tok = blockIdx.x * CE_WARPS + warp;

    const float* hrow = g_hs + (size_t)tok * HH;
    float s0 = 0.f, s1 = 0.f, s2 = 0.f, s3 = 0.f, s4 = 0.f;
    for (int k = lane; k < HH; k += 32) {
        float hv = hrow[k];
        const float* ur = U + k * CC;
        s0 += hv * ur[0]; s1 += hv * ur[1]; s2 += hv * ur[2];
        s3 += hv * ur[3]; s4 += hv * ur[4];
    }
#pragma unroll
    for (int off = 16; off; off >>= 1) {
        s0 += __shfl_down_sync(0xffffffffu, s0, off);
        s1 += __shfl_down_sync(0xffffffffu, s1, off);
        s2 += __shfl_down_sync(0xffffffffu, s2, off);
        s3 += __shfl_down_sync(0xffffffffu, s3, off);
        s4 += __shfl_down_sync(0xffffffffu, s4, off);
    }
    if (lane == 0) {
        s0 += b2[0]; s1 += b2[1]; s2 += b2[2]; s3 += b2[3]; s4 += b2[4];
        float m = fmaxf(fmaxf(fmaxf(s0, s1), fmaxf(s2, s3)), s4);
        float sum = expf(s0 - m) + expf(s1 - m) + expf(s2 - m)
                  + expf(s3 - m) + expf(s4 - m);
        float lse = m + logf(sum);
        int lab = labels[tok];
        float lc = (lab == 0) ? s0 : (lab == 1) ? s1 : (lab == 2) ? s2
                 : (lab == 3) ? s3 : s4;
        float ce = lse - lc;
        int mk;
        if (g_mask_is_byte) mk = (((const unsigned char*)maskp)[tok] != 0);
        else                mk = (((const int*)maskp)[tok] != 0);
        ssum[warp] = mk ? (double)ce : 0.0;
        scnt[warp] = mk;
    }
    __syncthreads();
    if (threadIdx.x == 0) {
        double s = 0.0; int c = 0;
        for (int w = 0; w < CE_WARPS; ++w) { s += ssum[w]; c += scnt[w]; }
        g_bsum[blockIdx.x] = s;
        g_bcnt[blockIdx.x] = c;
    }
}

// Deterministic fixed-order reduction of block partials.
__global__ void red_k() {
    __shared__ double sd[256];
    __shared__ int    sc[256];
    int j = blockIdx.x;
    int i = threadIdx.x;
    double s = 0.0; int c = 0;
    if (i < RED_PER) {
        s = g_bsum[j * RED_PER + i];
        c = g_bcnt[j * RED_PER + i];
    }
    sd[i] = s; sc[i] = c;
    __syncthreads();
    for (int off = 128; off; off >>= 1) {
        if (i < off) { sd[i] += sd[i + off]; sc[i] += sc[i + off]; }
        __syncthreads();
    }
    if (i == 0) { g_rsum[j] = sd[0]; g_rcnt[j] = sc[0]; }
}

__global__ void fin_k(float* out) {
    if (threadIdx.x == 0 && blockIdx.x == 0) {
        double s = 0.0; int c = 0;
        for (int j = 0; j < RED_BLOCKS; ++j) { s += g_rsum[j]; c += g_rcnt[j]; }
        out[0] = (float)(s / (double)c);
    }
}

// ----------------- launcher -----------------
extern "C" void kernel_launch(void* const* d_in, const int* in_sizes, int n_in,
                              void* d_out, int out_size)
{
    const int*   tokens = (const int*)d_in[0];
    const int*   labels = (const int*)d_in[1];
    const void*  mask   = d_in[2];                 // bool (byte or i32, detected)
    const float* emb    = (const float*)d_in[3];
    const float* Wx     = (const float*)d_in[4];
    const float* Wh     = (const float*)d_in[5];
    const float* bias   = (const float*)d_in[6];
    const float* U      = (const float*)d_in[7];
    const float* b2     = (const float*)d_in[8];
    float* out = (float*)d_out;

    init_k<<<(HH * BB + 255) / 256, 256>>>();
    detect_k<<<(TOKENS / 4 + 255) / 256, 256>>>((const unsigned int*)mask);
    wpad_k<<<(KPAD * NZP + 255) / 256, 256>>>(Wx, Wh);
    gather_k<<<(TT * EE * BB + 255) / 256, 256>>>(tokens, emb);

    dim3 ggrid(BB / GM, NZP / GN);                 // (8, 17)
    for (int t = 0; t < TT; ++t) {
        lstm_gemm_k<<<ggrid, 256>>>(t);
        gate_k<<<(BB * HH) / 256, 256>>>(t, bias);
    }

    ce_k<<<CE_BLOCKS, CE_WARPS * 32>>>(U, b2, labels, mask);
    red_k<<<RED_BLOCKS, 256>>>();
    fin_k<<<1, 32>>>(out);
    (void)in_sizes; (void)n_in; (void)out_size;
}

// round 5
// speedup vs baseline: 1.5290x; 1.4699x over previous
#include <cuda_runtime.h>
#include <cstdint>
#include <math.h>

// Problem constants
constexpr int BB = 1024;
constexpr int TT = 120;
constexpr int EE = 50;
constexpr int HH = 300;
constexpr int CC = 5;
constexpr int KTOT = EE + HH;        // 350
constexpr int KPAD = 352;            // 22 * 16
constexpr int NZ = 4 * HH;           // 1200
constexpr int NZP = 1224;            // 17 * 72 padded cols

// GEMM tiling
constexpr int GM = 128;              // rows per block
constexpr int GN = 72;               // cols per block
constexpr int KC = 16;               // K chunk (double buffered)
constexpr int NCHUNK = KPAD / KC;    // 22

// CE kernel
constexpr int TOKENS = BB * TT;                   // 122880
constexpr int CE_TB = 128;                        // tokens (threads) per block
constexpr int CE_BLOCKS = TOKENS / CE_TB;         // 960

// ----------------- device scratch (no cudaMalloc allowed) -----------------
__device__ float  g_xT[TT * EE * BB];      // x transposed  [t][e][b]   24.6 MB
__device__ float  g_W[KPAD * NZP];         // padded [Wx;Wh]            1.72 MB
__device__ float  g_hT[2][HH * BB];        // h transposed  [h][b], x2
__device__ float  g_c[HH * BB];            // cell state    [p][b]
__device__ float  g_zT[NZP * BB];          // z transposed  [col][b]    5.0 MB
__device__ float  g_hs[TT * HH * BB];      // hidden states [t][h][b]   147 MB
__device__ double g_bsum[CE_BLOCKS];
__device__ int    g_bcnt[CE_BLOCKS];
__device__ int    g_mask_is_byte;          // 0 at load; set to 1 iff byte bools

// ----------------- helpers -----------------
__device__ __forceinline__ void fma2(unsigned long long& d,
                                     unsigned long long a,
                                     unsigned long long b) {
    asm("fma.rn.f32x2 %0, %1, %2, %0;" : "+l"(d) : "l"(a), "l"(b));
}

__device__ __forceinline__ float rcp_fast(float x) {
    float y;
    asm("rcp.approx.f32 %0, %1;" : "=f"(y) : "f"(x));
    return y;
}

// sigmoid via EX2 + RCP (2 MUFU, ~1e-6 accurate)
__device__ __forceinline__ float sig_fast(float x) {
    return rcp_fast(1.0f + __expf(-x));
}

// tanh via single exp: (e^{2x}-1)/(e^{2x}+1), clamped (2 MUFU, ~1e-6)
__device__ __forceinline__ float tanh_fast(float x) {
    float xc = fminf(fmaxf(x, -15.0f), 15.0f);
    float e = __expf(2.0f * xc);
    return (e - 1.0f) * rcp_fast(e + 1.0f);
}

// ----------------- setup kernels -----------------

// Zero states; detect mask storage (sets flag to 1 only; idempotent,
// deterministic across graph replays for fixed input).
__global__ void initdetect_k(const unsigned int* __restrict__ mw) {
    int idx = blockIdx.x * blockDim.x + threadIdx.x;
    if (idx < HH * BB) {
        g_hT[0][idx] = 0.f;
        g_hT[1][idx] = 0.f;
        g_c[idx] = 0.f;
    }
    if (idx < TOKENS / 4) {
        if (mw[idx] > 1u) g_mask_is_byte = 1;   // benign race, same value
    }
}

// Build padded weight matrix g_W[k][c]: rows 0..49 = Wx, 50..349 = Wh, rest 0.
__global__ void wpad_k(const float* __restrict__ Wx,
                       const float* __restrict__ Wh) {
    int idx = blockIdx.x * blockDim.x + threadIdx.x;
    if (idx < KPAD * NZP) {
        int k = idx / NZP, c = idx % NZP;
        float v = 0.f;
        if (c < NZ) {
            if (k < EE)        v = Wx[k * NZ + c];
            else if (k < KTOT) v = Wh[(k - EE) * NZ + c];
        }
        g_W[idx] = v;
    }
}

// Gather embeddings transposed via smem transpose.
// grid (TT, BB/64), 256 threads. Coalesced emb-row reads, coalesced xT writes.
__global__ void gather_k(const int* __restrict__ tokens,
                         const float* __restrict__ emb) {
    __shared__ int   toks[64];
    __shared__ float tile[EE][65];
    const int t = blockIdx.x;
    const int b0 = blockIdx.y * 64;
    const int tid = threadIdx.x;
    const int warp = tid >> 5, lane = tid & 31;

    if (tid < 64) toks[tid] = tokens[(b0 + tid) * TT + t];
    __syncthreads();

    for (int row = warp; row < 64; row += 8) {
        const float* er = emb + (size_t)toks[row] * EE;
        for (int e = lane; e < EE; e += 32) tile[e][row] = er[e];
    }
    __syncthreads();

    for (int e = warp; e < EE; e += 8) {
        float* dst = g_xT + ((size_t)t * EE + e) * BB + b0;
        dst[lane]      = tile[e][lane];
        dst[lane + 32] = tile[e][lane + 32];
    }
}

// ----------------- per-step GEMM: zT = ([x_t | h_prev] @ Wpad)^T ------------
// grid (8, 17), 256 threads. Thread (tx=tid&7, ty=tid>>3):
//   rows r0 + ty*4 .. +3 (2 f32x2 pairs), cols c0 + tx + 8j, j=0..8.
// Double-buffered KC=16 stages.
__global__ __launch_bounds__(256) void lstm_gemm_k(int t) {
    __shared__ __align__(16) float As[2][KC][GM];     // 16 KB
    __shared__ __align__(16) float Ws[2][KC][GN][2];  // 18 KB

    const int tid = threadIdx.x;
    const int tx = tid & 7;
    const int ty = tid >> 3;           // 0..31
    const int r0 = blockIdx.x * GM;
    const int c0 = blockIdx.y * GN;
    const float* __restrict__ hT = g_hT[t & 1];

    unsigned long long acc[2][9];
#pragma unroll
    for (int p = 0; p < 2; ++p)
#pragma unroll
        for (int j = 0; j < 9; ++j) acc[p][j] = 0ull;

    // stage loader
    auto load_stage = [&](int s, int k0) {
        // A: 16x128 = 2048 elems, 8 per thread, r coalesced in low 7 bits
        {
            const int r = tid & 127;
            const int khalf = tid >> 7;            // 0 or 1
#pragma unroll
            for (int n = 0; n < 8; ++n) {
                int kc = (n << 1) + khalf;
                int k = k0 + kc;
                float v = 0.f;
                if (k < EE)        v = g_xT[((size_t)t * EE + k) * BB + r0 + r];
                else if (k < KTOT) v = hT[(k - EE) * BB + r0 + r];
                As[s][kc][r] = v;
            }
        }
        // W: 16x72 = 1152 elems, duplicated for f32x2
        {
#pragma unroll
            for (int n = 0; n < 5; ++n) {
                int i = tid + (n << 8);
                if (i < KC * GN) {
                    int j = i % GN;
                    int kc = i / GN;
                    float v = g_W[(k0 + kc) * NZP + c0 + j];
                    Ws[s][kc][j][0] = v;
                    Ws[s][kc][j][1] = v;
                }
            }
        }
    };

    load_stage(0, 0);
    __syncthreads();

    const int ty4 = ty * 4;
    for (int chunk = 0; chunk < NCHUNK; ++chunk) {
        const int cur = chunk & 1;
        if (chunk + 1 < NCHUNK) load_stage(cur ^ 1, (chunk + 1) * KC);

#pragma unroll
        for (int kc = 0; kc < KC; ++kc) {
            unsigned long long a0 =
                *reinterpret_cast<const unsigned long long*>(&As[cur][kc][ty4]);
            unsigned long long a1 =
                *reinterpret_cast<const unsigned long long*>(&As[cur][kc][ty4 + 2]);
#pragma unroll
            for (int j = 0; j < 9; ++j) {
                unsigned long long w =
                    *reinterpret_cast<const unsigned long long*>(
                        &Ws[cur][kc][tx + 8 * j][0]);
                fma2(acc[0][j], a0, w);
                fma2(acc[1][j], a1, w);
            }
        }
        __syncthreads();
    }

    // Epilogue: packed 8-byte stores into transposed z.
#pragma unroll
    for (int p = 0; p < 2; ++p) {
#pragma unroll
        for (int j = 0; j < 9; ++j) {
            int col = c0 + tx + 8 * j;
            int row = r0 + ty4 + p * 2;
            *reinterpret_cast<unsigned long long*>(&g_zT[(size_t)col * BB + row])
                = acc[p][j];
        }
    }
}

// ----------------- per-step gate/update kernel (all coalesced) --------------
// grid 1200 blocks x 256: block -> p = blk>>2 (uniform), b = (blk&3)*256+tid.
__global__ void gate_k(int t, const float* __restrict__ bias) {
    const int p = blockIdx.x >> 2;
    const int b = ((blockIdx.x & 3) << 8) + threadIdx.x;

    float iv = g_zT[(size_t)(p)            * BB + b] + bias[p];
    float jv = g_zT[(size_t)(HH + p)       * BB + b] + bias[HH + p];
    float fv = g_zT[(size_t)(2 * HH + p)   * BB + b] + bias[2 * HH + p];
    float ov = g_zT[(size_t)(3 * HH + p)   * BB + b] + bias[3 * HH + p];

    const int sidx = p * BB + b;
    float cold = g_c[sidx];
    float cn = sig_fast(fv + 1.0f) * cold + sig_fast(iv) * tanh_fast(jv);
    float hn = sig_fast(ov) * tanh_fast(cn);
    g_c[sidx] = cn;
    g_hs[((size_t)t * HH + p) * BB + b] = hn;
    g_hT[(t + 1) & 1][sidx] = hn;
}

// ----------------- CE: projection + log-softmax + masked sum ----------------
// grid 960 blocks x 128 threads; block -> (t = blk/8, b0 = (blk%8)*128).
__global__ void ce_k(const float* __restrict__ U, const float* __restrict__ b2,
                     const int* __restrict__ labels,
                     const void* __restrict__ maskp)
{
    __shared__ float Us[HH * CC];
    __shared__ float b2s[CC];
    __shared__ double sd[CE_TB];
    __shared__ int    sc[CE_TB];

    const int tid = threadIdx.x;
    const int t = blockIdx.x >> 3;
    const int b = ((blockIdx.x & 7) << 7) + tid;

    for (int i = tid; i < HH * CC; i += CE_TB) Us[i] = U[i];
    if (tid < CC) b2s[tid] = b2[tid];
    __syncthreads();

    float s0 = b2s[0], s1 = b2s[1], s2 = b2s[2], s3 = b2s[3], s4 = b2s[4];
    const float* hp = g_hs + (size_t)t * HH * BB + b;
#pragma unroll 4
    for (int k = 0; k < HH; ++k) {
        float hv = hp[(size_t)k * BB];
        const float* ur = &Us[k * CC];
        s0 += hv * ur[0]; s1 += hv * ur[1]; s2 += hv * ur[2];
        s3 += hv * ur[3]; s4 += hv * ur[4];
    }

    float m = fmaxf(fmaxf(fmaxf(s0, s1), fmaxf(s2, s3)), s4);
    float sum = __expf(s0 - m) + __expf(s1 - m) + __expf(s2 - m)
              + __expf(s3 - m) + __expf(s4 - m);
    float lse = m + __logf(sum);
    int lab = labels[b * TT + t];
    float lc = (lab == 0) ? s0 : (lab == 1) ? s1 : (lab == 2) ? s2
             : (lab == 3) ? s3 : s4;
    float ce = lse - lc;
    int mk;
    if (g_mask_is_byte) mk = (((const unsigned char*)maskp)[b * TT + t] != 0);
    else                mk = (((const int*)maskp)[b * TT + t] != 0);

    sd[tid] = mk ? (double)ce : 0.0;
    sc[tid] = mk;
    __syncthreads();
    for (int off = CE_TB / 2; off; off >>= 1) {
        if (tid < off) { sd[tid] += sd[tid + off]; sc[tid] += sc[tid + off]; }
        __syncthreads();
    }
    if (tid == 0) { g_bsum[blockIdx.x] = sd[0]; g_bcnt[blockIdx.x] = sc[0]; }
}

// Deterministic final reduction over 960 partials.
__global__ void fin_k(float* out) {
    __shared__ double sd[256];
    __shared__ int    sc[256];
    int i = threadIdx.x;
    double s = 0.0; int c = 0;
    for (int j = i; j < CE_BLOCKS; j += 256) { s += g_bsum[j]; c += g_bcnt[j]; }
    sd[i] = s; sc[i] = c;
    __syncthreads();
    for (int off = 128; off; off >>= 1) {
        if (i < off) { sd[i] += sd[i + off]; sc[i] += sc[i + off]; }
        __syncthreads();
    }
    if (i == 0) out[0] = (float)(sd[0] / (double)sc[0]);
}

// ----------------- launcher -----------------
extern "C" void kernel_launch(void* const* d_in, const int* in_sizes, int n_in,
                              void* d_out, int out_size)
{
    const int*   tokens = (const int*)d_in[0];
    const int*   labels = (const int*)d_in[1];
    const void*  mask   = d_in[2];                 // bool (byte or i32, detected)
    const float* emb    = (const float*)d_in[3];
    const float* Wx     = (const float*)d_in[4];
    const float* Wh     = (const float*)d_in[5];
    const float* bias   = (const float*)d_in[6];
    const float* U      = (const float*)d_in[7];
    const float* b2     = (const float*)d_in[8];
    float* out = (float*)d_out;

    initdetect_k<<<(HH * BB + 255) / 256, 256>>>((const unsigned int*)mask);
    wpad_k<<<(KPAD * NZP + 255) / 256, 256>>>(Wx, Wh);
    gather_k<<<dim3(TT, BB / 64), 256>>>(tokens, emb);

    dim3 ggrid(BB / GM, NZP / GN);                 // (8, 17) = 136 blocks
    for (int t = 0; t < TT; ++t) {
        lstm_gemm_k<<<ggrid, 256>>>(t);            // t=0 is launch #3 (profiled)
        gate_k<<<HH * 4, 256>>>(t, bias);
    }

    ce_k<<<CE_BLOCKS, CE_TB>>>(U, b2, labels, mask);
    fin_k<<<1, 256>>>(out);
    (void)in_sizes; (void)n_in; (void)out_size;
}

// round 7
// speedup vs baseline: 2.7096x; 1.7722x over previous
#include <cuda_runtime.h>
#include <cstdint>
#include <math.h>

// Problem constants
constexpr int BB = 1024;
constexpr int TT = 120;
constexpr int EE = 50;
constexpr int HH = 300;
constexpr int CC = 5;
constexpr int KTOT = EE + HH;        // 350
constexpr int KPAD = 352;            // 22 * 16
constexpr int NZ = 4 * HH;           // 1200
constexpr int NZP = 1224;            // 17 * 72 padded cols

// GEMM tiling
constexpr int GM = 128;              // rows per block
constexpr int GN = 72;               // cols per block
constexpr int KC = 16;               // K chunk (cp.async double buffered)
constexpr int NCHUNK = KPAD / KC;    // 22

// CE kernel
constexpr int TOKENS = BB * TT;                   // 122880
constexpr int CE_TB = 128;
constexpr int CE_BLOCKS = TOKENS / CE_TB;         // 960

// ----------------- device scratch (no cudaMalloc allowed) -----------------
__device__ float  g_xT[TT * EE * BB];        // x transposed [t][e][b]   24.6 MB
__device__ float2 g_Wdup[KPAD * NZP];        // padded W, duplicated      3.45 MB
__device__ float  g_hT[2][HH * BB];          // h transposed [h][b], x2
__device__ float  g_c[HH * BB];              // cell state   [p][b]
__device__ float  g_zT[NZP * BB];            // z transposed [col][b]     5.0 MB
__device__ float  g_hs[TT * HH * BB];        // hidden states [t][h][b]   147 MB
__device__ double g_bsum[CE_BLOCKS];
__device__ int    g_bcnt[CE_BLOCKS];
__device__ int    g_mask_is_byte;

// ----------------- helpers -----------------
__device__ __forceinline__ void fma2(unsigned long long& d,
                                     unsigned long long a,
                                     unsigned long long b) {
    asm("fma.rn.f32x2 %0, %1, %2, %0;" : "+l"(d) : "l"(a), "l"(b));
}

__device__ __forceinline__ float rcp_fast(float x) {
    float y;
    asm("rcp.approx.f32 %0, %1;" : "=f"(y) : "f"(x));
    return y;
}

// exp(x) with ZERO MUFU: FMA-only range reduction + 2^f poly + exponent add.
// Domain clamped to |x*log2e| <= 30 (enough for saturated gates, no overflow).
__device__ __forceinline__ float exp_fma(float x) {
    float x2 = x * 1.4426950408889634f;
    x2 = fminf(fmaxf(x2, -30.0f), 30.0f);
    float biased = x2 + 12582912.0f;            // 1.5 * 2^23 (round to nearest)
    int   ni = __float_as_int(biased) - 0x4B400000;
    float n = biased - 12582912.0f;
    float f = x2 - n;
    float p = 1.5403530e-4f;                     // 2^f Taylor, |f|<=0.5
    p = fmaf(p, f, 1.3333558e-3f);
    p = fmaf(p, f, 9.6181291e-3f);
    p = fmaf(p, f, 5.5504109e-2f);
    p = fmaf(p, f, 2.4022651e-1f);
    p = fmaf(p, f, 6.9314718e-1f);
    p = fmaf(p, f, 1.0f);
    return __int_as_float(__float_as_int(p) + (ni << 23));
}

__device__ __forceinline__ void cp16(uint32_t dst_smem, const void* src, int srcsize) {
    asm volatile("cp.async.cg.shared.global [%0], [%1], 16, %2;"
                 :: "r"(dst_smem), "l"(src), "r"(srcsize));
}
__device__ __forceinline__ void cp_commit() {
    asm volatile("cp.async.commit_group;");
}
template <int N>
__device__ __forceinline__ void cp_wait() {
    asm volatile("cp.async.wait_group %0;" :: "n"(N));
}

// ----------------- setup kernels -----------------

__global__ void initdetect_k(const unsigned int* __restrict__ mw) {
    int idx = blockIdx.x * blockDim.x + threadIdx.x;
    if (idx < HH * BB) {
        g_hT[0][idx] = 0.f;
        g_hT[1][idx] = 0.f;
        g_c[idx] = 0.f;
    }
    if (idx < TOKENS / 4) {
        if (mw[idx] > 1u) g_mask_is_byte = 1;   // benign race, same value
    }
}

// Padded + duplicated weights: g_Wdup[k*NZP+c] = (w, w).
__global__ void wpad_k(const float* __restrict__ Wx,
                       const float* __restrict__ Wh) {
    int idx = blockIdx.x * blockDim.x + threadIdx.x;
    if (idx < KPAD * NZP) {
        int k = idx / NZP, c = idx % NZP;
        float v = 0.f;
        if (c < NZ) {
            if (k < EE)        v = Wx[k * NZ + c];
            else if (k < KTOT) v = Wh[(k - EE) * NZ + c];
        }
        g_Wdup[idx] = make_float2(v, v);
    }
}

// Gather embeddings transposed via smem transpose.
__global__ void gather_k(const int* __restrict__ tokens,
                         const float* __restrict__ emb) {
    __shared__ int   toks[64];
    __shared__ float tile[EE][65];
    const int t = blockIdx.x;
    const int b0 = blockIdx.y * 64;
    const int tid = threadIdx.x;
    const int warp = tid >> 5, lane = tid & 31;

    if (tid < 64) toks[tid] = tokens[(b0 + tid) * TT + t];
    __syncthreads();
    for (int row = warp; row < 64; row += 8) {
        const float* er = emb + (size_t)toks[row] * EE;
        for (int e = lane; e < EE; e += 32) tile[e][row] = er[e];
    }
    __syncthreads();
    for (int e = warp; e < EE; e += 8) {
        float* dst = g_xT + ((size_t)t * EE + e) * BB + b0;
        dst[lane]      = tile[e][lane];
        dst[lane + 32] = tile[e][lane + 32];
    }
}

// ----------------- per-step GEMM: zT = ([x_t | h_prev] @ W)^T ---------------
// grid (8, 17), 256 threads. Thread (tx=tid&7, ty=tid>>3):
//   rows r0+ty*4..+3 (2 f32x2 pairs), cols c0+tx+8j, j=0..8.
// cp.async double-buffered, KC=16. Static smem 34 KB.
__global__ __launch_bounds__(256) void lstm_gemm_k(int t) {
    __shared__ __align__(16) float As[2][KC][GM];     // 16 KB
    __shared__ __align__(16) float Ws[2][KC][GN][2];  // 18 KB

    const int tid = threadIdx.x;
    const int tx = tid & 7;
    const int ty = tid >> 3;
    const int r0 = blockIdx.x * GM;
    const int c0 = blockIdx.y * GN;
    const float* __restrict__ hT = g_hT[t & 1];
    const float* __restrict__ xTt = g_xT + (size_t)t * EE * BB;

    const uint32_t sAs = (uint32_t)__cvta_generic_to_shared(&As[0][0][0]);
    const uint32_t sWs = (uint32_t)__cvta_generic_to_shared(&Ws[0][0][0][0]);

    unsigned long long acc[2][9];
#pragma unroll
    for (int p = 0; p < 2; ++p)
#pragma unroll
        for (int j = 0; j < 9; ++j) acc[p][j] = 0ull;

    // stage loader: A = 16x128 floats = 512 x 16B ops (2/thread),
    //               W = 16x72 float2  = 576 x 16B ops (2.25/thread).
    auto load_stage = [&](int s, int k0) {
        // A tile
#pragma unroll
        for (int n = 0; n < 2; ++n) {
            int idx = tid + (n << 8);              // 0..511
            int kc = idx >> 5;                     // 0..15
            int seg = idx & 31;                    // 16B segment in 128-float row
            int k = k0 + kc;
            const float* src;
            int sz = 16;
            if (k < EE)        src = xTt + (size_t)k * BB + r0 + seg * 4;
            else if (k < KTOT) src = hT + (size_t)(k - EE) * BB + r0 + seg * 4;
            else             { src = hT; sz = 0; }  // zero-fill pad rows
            cp16(sAs + (uint32_t)(s * (KC * GM) + kc * GM + seg * 4) * 4, src, sz);
        }
        // W tile (already duplicated in global; straight 16B copies)
        const float2* wbase = g_Wdup + (size_t)k0 * NZP + c0;
#pragma unroll
        for (int n = 0; n < 3; ++n) {
            int idx = tid + (n << 8);
            if (idx < KC * 36) {                   // 576 ops, 36 x 16B per row
                int kc = idx / 36;
                int off = idx - kc * 36;
                const void* src = (const void*)(wbase + (size_t)kc * NZP + off * 2);
                cp16(sWs + (uint32_t)(s * (KC * GN * 2) + kc * (GN * 2)) * 4
                         + (uint32_t)off * 16, src, 16);
            }
        }
    };

    load_stage(0, 0);
    cp_commit();

    const int ty4 = ty * 4;
    for (int chunk = 0; chunk < NCHUNK; ++chunk) {
        const int cur = chunk & 1;
        if (chunk + 1 < NCHUNK) {
            load_stage(cur ^ 1, (chunk + 1) * KC);
            cp_commit();
            cp_wait<1>();          // stage `cur` resident
        } else {
            cp_wait<0>();
        }
        __syncthreads();

#pragma unroll
        for (int kc = 0; kc < KC; ++kc) {
            unsigned long long a0 =
                *reinterpret_cast<const unsigned long long*>(&As[cur][kc][ty4]);
            unsigned long long a1 =
                *reinterpret_cast<const unsigned long long*>(&As[cur][kc][ty4 + 2]);
#pragma unroll
            for (int j = 0; j < 9; ++j) {
                unsigned long long w =
                    *reinterpret_cast<const unsigned long long*>(
                        &Ws[cur][kc][tx + 8 * j][0]);
                fma2(acc[0][j], a0, w);
                fma2(acc[1][j], a1, w);
            }
        }
        __syncthreads();   // reads of buffer `cur` done before it is refilled
    }

    // Epilogue: packed 8-byte stores into transposed z.
#pragma unroll
    for (int p = 0; p < 2; ++p) {
#pragma unroll
        for (int j = 0; j < 9; ++j) {
            int col = c0 + tx + 8 * j;
            int row = r0 + ty4 + p * 2;
            *reinterpret_cast<unsigned long long*>(&g_zT[(size_t)col * BB + row])
                = acc[p][j];
        }
    }
}

// ----------------- per-step gate/update kernel ------------------------------
// All coalesced; 2 MUFU (RCP) per element, exp on FMA pipe.
__global__ void gate_k(int t, const float* __restrict__ bias) {
    const int p = blockIdx.x >> 2;
    const int b = ((blockIdx.x & 3) << 8) + threadIdx.x;

    float iv = g_zT[(size_t)(p)          * BB + b] + bias[p];
    float jv = g_zT[(size_t)(HH + p)     * BB + b] + bias[HH + p];
    float fv = g_zT[(size_t)(2 * HH + p) * BB + b] + bias[2 * HH + p];
    float ov = g_zT[(size_t)(3 * HH + p) * BB + b] + bias[3 * HH + p];

    const int sidx = p * BB + b;
    float c = g_c[sidx];

    float ef = exp_fma(-(fv + 1.0f));    // for sig(f+1)
    float ei = exp_fma(-iv);             // for sig(i)
    float ej = exp_fma(2.0f * jv);       // for tanh(j)
    float eo = exp_fma(-ov);             // for sig(o)

    float Af = 1.0f + ef;
    float Ai = 1.0f + ei;
    float Aj = ej + 1.0f;
    float Nj = ej - 1.0f;
    // cn = c/Af + Nj/(Ai*Aj), one reciprocal
    float AiAj = Ai * Aj;
    float num = fmaf(c, AiAj, Nj * Af);
    float cn = num * rcp_fast(Af * AiAj);

    float ec = exp_fma(2.0f * cn);
    // h = sig(o) * tanh(cn) = (ec-1) / ((1+eo)*(ec+1)), one reciprocal
    float hn = (ec - 1.0f) * rcp_fast((1.0f + eo) * (ec + 1.0f));

    g_c[sidx] = cn;
    g_hs[((size_t)t * HH + p) * BB + b] = hn;
    g_hT[(t + 1) & 1][sidx] = hn;
}

// ----------------- CE: projection + log-softmax + masked sum ----------------
__global__ void ce_k(const float* __restrict__ U, const float* __restrict__ b2,
                     const int* __restrict__ labels,
                     const void* __restrict__ maskp)
{
    __shared__ float Us[HH * CC];
    __shared__ float b2s[CC];
    __shared__ double sd[CE_TB];
    __shared__ int    sc[CE_TB];

    const int tid = threadIdx.x;
    const int t = blockIdx.x >> 3;
    const int b = ((blockIdx.x & 7) << 7) + tid;

    for (int i = tid; i < HH * CC; i += CE_TB) Us[i] = U[i];
    if (tid < CC) b2s[tid] = b2[tid];
    __syncthreads();

    float s0 = b2s[0], s1 = b2s[1], s2 = b2s[2], s3 = b2s[3], s4 = b2s[4];
    const float* hp = g_hs + (size_t)t * HH * BB + b;
#pragma unroll 4
    for (int k = 0; k < HH; ++k) {
        float hv = hp[(size_t)k * BB];
        const float* ur = &Us[k * CC];
        s0 += hv * ur[0]; s1 += hv * ur[1]; s2 += hv * ur[2];
        s3 += hv * ur[3]; s4 += hv * ur[4];
    }

    float m = fmaxf(fmaxf(fmaxf(s0, s1), fmaxf(s2, s3)), s4);
    float sum = __expf(s0 - m) + __expf(s1 - m) + __expf(s2 - m)
              + __expf(s3 - m) + __expf(s4 - m);
    float lse = m + __logf(sum);
    int lab = labels[b * TT + t];
    float lc = (lab == 0) ? s0 : (lab == 1) ? s1 : (lab == 2) ? s2
             : (lab == 3) ? s3 : s4;
    float ce = lse - lc;
    int mk;
    if (g_mask_is_byte) mk = (((const unsigned char*)maskp)[b * TT + t] != 0);
    else                mk = (((const int*)maskp)[b * TT + t] != 0);

    sd[tid] = mk ? (double)ce : 0.0;
    sc[tid] = mk;
    __syncthreads();
    for (int off = CE_TB / 2; off; off >>= 1) {
        if (tid < off) { sd[tid] += sd[tid + off]; sc[tid] += sc[tid + off]; }
        __syncthreads();
    }
    if (tid == 0) { g_bsum[blockIdx.x] = sd[0]; g_bcnt[blockIdx.x] = sc[0]; }
}

__global__ void fin_k(float* out) {
    __shared__ double sd[256];
    __shared__ int    sc[256];
    int i = threadIdx.x;
    double s = 0.0; int c = 0;
    for (int j = i; j < CE_BLOCKS; j += 256) { s += g_bsum[j]; c += g_bcnt[j]; }
    sd[i] = s; sc[i] = c;
    __syncthreads();
    for (int off = 128; off; off >>= 1) {
        if (i < off) { sd[i] += sd[i + off]; sc[i] += sc[i + off]; }
        __syncthreads();
    }
    if (i == 0) out[0] = (float)(sd[0] / (double)sc[0]);
}

// ----------------- launcher -----------------
extern "C" void kernel_launch(void* const* d_in, const int* in_sizes, int n_in,
                              void* d_out, int out_size)
{
    const int*   tokens = (const int*)d_in[0];
    const int*   labels = (const int*)d_in[1];
    const void*  mask   = d_in[2];
    const float* emb    = (const float*)d_in[3];
    const float* Wx     = (const float*)d_in[4];
    const float* Wh     = (const float*)d_in[5];
    const float* bias   = (const float*)d_in[6];
    const float* U      = (const float*)d_in[7];
    const float* b2     = (const float*)d_in[8];
    float* out = (float*)d_out;

    initdetect_k<<<(HH * BB + 255) / 256, 256>>>((const unsigned int*)mask);
    wpad_k<<<(KPAD * NZP + 255) / 256, 256>>>(Wx, Wh);
    gather_k<<<dim3(TT, BB / 64), 256>>>(tokens, emb);

    dim3 ggrid(BB / GM, NZP / GN);                 // (8, 17) = 136 blocks
    for (int t = 0; t < TT; ++t) {
        lstm_gemm_k<<<ggrid, 256>>>(t);            // t=0 is launch #3 (profiled)
        gate_k<<<HH * 4, 256>>>(t, bias);
    }

    ce_k<<<CE_BLOCKS, CE_TB>>>(U, b2, labels, mask);
    fin_k<<<1, 256>>>(out);
    (void)in_sizes; (void)n_in; (void)out_size;
}

// round 8
// speedup vs baseline: 2.8155x; 1.0391x over previous
#include <cuda_runtime.h>
#include <cstdint>
#include <math.h>

// Problem constants
constexpr int BB = 1024;
constexpr int TT = 120;
constexpr int EE = 50;
constexpr int HH = 300;
constexpr int CC = 5;
constexpr int KTOT = EE + HH;        // 350
constexpr int KPAD = 352;            // 22 * 16
constexpr int NZ = 4 * HH;           // 1200
constexpr int NZP = 1224;            // 17 * 72 padded (permuted) cols

// GEMM tiling
constexpr int GM = 128;              // rows per block
constexpr int GN = 72;               // cols per block = 18 positions * 4 gates
constexpr int KC = 16;               // K chunk (cp.async double buffered)
constexpr int NCHUNK = KPAD / KC;    // 22
constexpr int POSB = 18;             // positions per block

// CE kernel
constexpr int TOKENS = BB * TT;                   // 122880
constexpr int CE_TB = 128;
constexpr int CE_BLOCKS = TOKENS / CE_TB;         // 960

// ----------------- device scratch (no cudaMalloc allowed) -----------------
__device__ float  g_xT[TT * EE * BB];        // x transposed [t][e][b]   24.6 MB
__device__ float2 g_Wdup[KPAD * NZP];        // permuted+dup W            3.45 MB
__device__ float  g_biasP[NZP];              // permuted bias
__device__ float  g_hT[2][HH * BB];          // h transposed [h][b], x2
__device__ float  g_c[HH * BB];              // cell state   [p][b]
__device__ float  g_hs[TT * HH * BB];        // hidden states [t][h][b]   147 MB
__device__ double g_bsum[CE_BLOCKS];
__device__ int    g_bcnt[CE_BLOCKS];
__device__ int    g_mask_is_byte;

// ----------------- helpers -----------------
__device__ __forceinline__ void fma2(unsigned long long& d,
                                     unsigned long long a,
                                     unsigned long long b) {
    asm("fma.rn.f32x2 %0, %1, %2, %0;" : "+l"(d) : "l"(a), "l"(b));
}

__device__ __forceinline__ float rcp_fast(float x) {
    float y;
    asm("rcp.approx.f32 %0, %1;" : "=f"(y) : "f"(x));
    return y;
}

// exp(x) with zero MUFU: FMA-only range reduction + 2^f poly + exponent add.
__device__ __forceinline__ float exp_fma(float x) {
    float x2 = x * 1.4426950408889634f;
    x2 = fminf(fmaxf(x2, -30.0f), 30.0f);
    float biased = x2 + 12582912.0f;            // 1.5 * 2^23
    int   ni = __float_as_int(biased) - 0x4B400000;
    float n = biased - 12582912.0f;
    float f = x2 - n;
    float p = 1.5403530e-4f;
    p = fmaf(p, f, 1.3333558e-3f);
    p = fmaf(p, f, 9.6181291e-3f);
    p = fmaf(p, f, 5.5504109e-2f);
    p = fmaf(p, f, 2.4022651e-1f);
    p = fmaf(p, f, 6.9314718e-1f);
    p = fmaf(p, f, 1.0f);
    return __int_as_float(__float_as_int(p) + (ni << 23));
}

// LSTM pointwise update (R7-validated math: FMA-exp + 2 RCP).
__device__ __forceinline__ void lstm_point(float iv, float jv, float fv, float ov,
                                           float c, float& cn, float& hn) {
    float ef = exp_fma(-(fv + 1.0f));
    float ei = exp_fma(-iv);
    float ej = exp_fma(2.0f * jv);
    float eo = exp_fma(-ov);
    float Af = 1.0f + ef;
    float Ai = 1.0f + ei;
    float Aj = ej + 1.0f;
    float Nj = ej - 1.0f;
    float AiAj = Ai * Aj;
    float num = fmaf(c, AiAj, Nj * Af);
    cn = num * rcp_fast(Af * AiAj);
    float ec = exp_fma(2.0f * cn);
    hn = (ec - 1.0f) * rcp_fast((1.0f + eo) * (ec + 1.0f));
}

__device__ __forceinline__ void cp16(uint32_t dst_smem, const void* src, int srcsize) {
    asm volatile("cp.async.cg.shared.global [%0], [%1], 16, %2;"
                 :: "r"(dst_smem), "l"(src), "r"(srcsize));
}
__device__ __forceinline__ void cp_commit() {
    asm volatile("cp.async.commit_group;");
}
template <int N>
__device__ __forceinline__ void cp_wait() {
    asm volatile("cp.async.wait_group %0;" :: "n"(N));
}

// ----------------- setup kernels -----------------

__global__ void initdetect_k(const unsigned int* __restrict__ mw) {
    int idx = blockIdx.x * blockDim.x + threadIdx.x;
    if (idx < HH * BB) {
        g_hT[0][idx] = 0.f;
        g_hT[1][idx] = 0.f;
        g_c[idx] = 0.f;
    }
    if (idx < TOKENS / 4) {
        if (mw[idx] > 1u) g_mask_is_byte = 1;   // benign race, same value
    }
}

// Permuted + padded + duplicated weights: permuted col c' = 4p+g,
// original col = g*300 + p. g_Wdup[k*NZP + c'] = (w, w). Also permuted bias.
__global__ void wpad_k(const float* __restrict__ Wx,
                       const float* __restrict__ Wh,
                       const float* __restrict__ bias) {
    int idx = blockIdx.x * blockDim.x + threadIdx.x;
    if (idx < KPAD * NZP) {
        int k = idx / NZP, cp = idx % NZP;
        float v = 0.f;
        if (cp < NZ) {
            int p = cp >> 2, g = cp & 3;
            int co = g * HH + p;
            if (k < EE)        v = Wx[k * NZ + co];
            else if (k < KTOT) v = Wh[(k - EE) * NZ + co];
        }
        g_Wdup[idx] = make_float2(v, v);
    }
    if (idx < NZP) {
        float v = 0.f;
        if (idx < NZ) v = bias[(idx & 3) * HH + (idx >> 2)];
        g_biasP[idx] = v;
    }
}

// Gather embeddings transposed via smem transpose.
__global__ void gather_k(const int* __restrict__ tokens,
                         const float* __restrict__ emb) {
    __shared__ int   toks[64];
    __shared__ float tile[EE][65];
    const int t = blockIdx.x;
    const int b0 = blockIdx.y * 64;
    const int tid = threadIdx.x;
    const int warp = tid >> 5, lane = tid & 31;

    if (tid < 64) toks[tid] = tokens[(b0 + tid) * TT + t];
    __syncthreads();
    for (int row = warp; row < 64; row += 8) {
        const float* er = emb + (size_t)toks[row] * EE;
        for (int e = lane; e < EE; e += 32) tile[e][row] = er[e];
    }
    __syncthreads();
    for (int e = warp; e < EE; e += 8) {
        float* dst = g_xT + ((size_t)t * EE + e) * BB + b0;
        dst[lane]      = tile[e][lane];
        dst[lane + 32] = tile[e][lane + 32];
    }
}

// --------- fused per-step kernel: GEMM + gates + state update --------------
// grid (8, 17), 256 threads. GEMM thread (tx=tid&7, ty=tid>>3):
//   rows r0+ty*4..+3 (2 f32x2 pairs), cols: pairs (2tx+16jg, 2tx+1+16jg)
//   jg=0..3, plus single col 64+tx. cp.async double-buffered KC=16.
// Epilogue: z-tile staged via smem (reusing stage buffers), full LSTM update.
constexpr int ZS_LD = 130;                                 // padded row stride
constexpr int SRAW_BYTES = GN * ZS_LD * 4;                 // 37440 >= 34816
__global__ __launch_bounds__(256) void lstm_step_k(int t) {
    __shared__ __align__(16) char s_raw[SRAW_BYTES];
    __shared__ float bias_s[GN];

    float* const Asb = reinterpret_cast<float*>(s_raw);            // [2][16][128]
    float* const Wsb = reinterpret_cast<float*>(s_raw + 16384);    // [2][16][72][2]
    float* const zs  = reinterpret_cast<float*>(s_raw);            // [72][130]

    const int tid = threadIdx.x;
    const int tx = tid & 7;
    const int ty = tid >> 3;
    const int r0 = blockIdx.x * GM;
    const int c0 = blockIdx.y * GN;
    const int pbase = blockIdx.y * POSB;
    const float* __restrict__ hT = g_hT[t & 1];
    const float* __restrict__ xTt = g_xT + (size_t)t * EE * BB;

    const uint32_t sAs = (uint32_t)__cvta_generic_to_shared(Asb);
    const uint32_t sWs = (uint32_t)__cvta_generic_to_shared(Wsb);

    // permuted bias for this block's 72 cols (separate smem, no aliasing)
    if (tid < GN) bias_s[tid] = g_biasP[c0 + tid];

    unsigned long long acc[2][9];
#pragma unroll
    for (int p = 0; p < 2; ++p)
#pragma unroll
        for (int j = 0; j < 9; ++j) acc[p][j] = 0ull;

    auto load_stage = [&](int s, int k0) {
        // A tile: 16x128 floats = 512 x 16B (2/thread)
#pragma unroll
        for (int n = 0; n < 2; ++n) {
            int idx = tid + (n << 8);
            int kc = idx >> 5;
            int seg = idx & 31;
            int k = k0 + kc;
            const float* src;
            int sz = 16;
            if (k < EE)        src = xTt + (size_t)k * BB + r0 + seg * 4;
            else if (k < KTOT) src = hT + (size_t)(k - EE) * BB + r0 + seg * 4;
            else             { src = hT; sz = 0; }
            cp16(sAs + (uint32_t)(s * (KC * GM) + kc * GM + seg * 4) * 4, src, sz);
        }
        // W tile: 16x72 float2 = 576 x 16B (2.25/thread)
        const float2* wbase = g_Wdup + (size_t)k0 * NZP + c0;
#pragma unroll
        for (int n = 0; n < 3; ++n) {
            int idx = tid + (n << 8);
            if (idx < KC * 36) {
                int kc = idx / 36;
                int off = idx - kc * 36;
                const void* src = (const void*)(wbase + (size_t)kc * NZP + off * 2);
                cp16(sWs + (uint32_t)(s * (KC * GN * 2) + kc * (GN * 2)) * 4
                         + (uint32_t)off * 16, src, 16);
            }
        }
    };

    load_stage(0, 0);
    cp_commit();

    const int ty4 = ty * 4;
    for (int chunk = 0; chunk < NCHUNK; ++chunk) {
        const int cur = chunk & 1;
        if (chunk + 1 < NCHUNK) {
            load_stage(cur ^ 1, (chunk + 1) * KC);
            cp_commit();
            cp_wait<1>();          // stage `cur` resident
        } else {
            cp_wait<0>();
        }
        __syncthreads();

        const float* Ab = Asb + cur * (KC * GM);
        const float* Wb = Wsb + cur * (KC * GN * 2);
#pragma unroll
        for (int kc = 0; kc < KC; ++kc) {
            ulonglong2 av = *reinterpret_cast<const ulonglong2*>(&Ab[kc * GM + ty4]);
            unsigned long long a0 = av.x, a1 = av.y;
            const float* wrow = Wb + kc * (GN * 2);
#pragma unroll
            for (int jg = 0; jg < 4; ++jg) {
                ulonglong2 wv = *reinterpret_cast<const ulonglong2*>(
                    &wrow[(2 * tx + 16 * jg) * 2]);
                fma2(acc[0][2 * jg],     a0, wv.x);
                fma2(acc[1][2 * jg],     a1, wv.x);
                fma2(acc[0][2 * jg + 1], a0, wv.y);
                fma2(acc[1][2 * jg + 1], a1, wv.y);
            }
            unsigned long long w8 = *reinterpret_cast<const unsigned long long*>(
                &wrow[(64 + tx) * 2]);
            fma2(acc[0][8], a0, w8);
            fma2(acc[1][8], a1, w8);
        }
        __syncthreads();   // stage `cur` fully consumed before refill/reuse
    }

    // ---- stage z-tile into smem (overlaps the now-dead stage buffers) ----
#pragma unroll
    for (int j = 0; j < 9; ++j) {
        int col = (j < 8) ? (2 * tx + 16 * (j >> 1) + (j & 1)) : (64 + tx);
#pragma unroll
        for (int p = 0; p < 2; ++p) {
            *reinterpret_cast<unsigned long long*>(
                &zs[col * ZS_LD + ty4 + 2 * p]) = acc[p][j];
        }
    }
    __syncthreads();

    // ---- gate math: thread -> (r = tid&127, half = tid>>7); 9 iters ----
    const int r = tid & 127;
    const int half = tid >> 7;
    const int b = r0 + r;
#pragma unroll
    for (int pp = 0; pp < 9; ++pp) {
        int pl = pp * 2 + half;
        int pg = pbase + pl;
        if (pg < HH) {
            float iv = zs[(4 * pl + 0) * ZS_LD + r] + bias_s[4 * pl + 0];
            float jv = zs[(4 * pl + 1) * ZS_LD + r] + bias_s[4 * pl + 1];
            float fv = zs[(4 * pl + 2) * ZS_LD + r] + bias_s[4 * pl + 2];
            float ov = zs[(4 * pl + 3) * ZS_LD + r] + bias_s[4 * pl + 3];
            int sidx = pg * BB + b;
            float c = g_c[sidx];
            float cn, hn;
            lstm_point(iv, jv, fv, ov, c, cn, hn);
            g_c[sidx] = cn;
            g_hs[((size_t)t * HH + pg) * BB + b] = hn;
            g_hT[(t + 1) & 1][sidx] = hn;
        }
    }
}

// ----------------- CE: projection + log-softmax + masked sum ----------------
__global__ void ce_k(const float* __restrict__ U, const float* __restrict__ b2,
                     const int* __restrict__ labels,
                     const void* __restrict__ maskp)
{
    __shared__ float Us[HH * CC];
    __shared__ float b2s[CC];
    __shared__ double sd[CE_TB];
    __shared__ int    sc[CE_TB];

    const int tid = threadIdx.x;
    const int t = blockIdx.x >> 3;
    const int b = ((blockIdx.x & 7) << 7) + tid;

    for (int i = tid; i < HH * CC; i += CE_TB) Us[i] = U[i];
    if (tid < CC) b2s[tid] = b2[tid];
    __syncthreads();

    float s0 = b2s[0], s1 = b2s[1], s2 = b2s[2], s3 = b2s[3], s4 = b2s[4];
    const float* hp = g_hs + (size_t)t * HH * BB + b;
#pragma unroll 4
    for (int k = 0; k < HH; ++k) {
        float hv = hp[(size_t)k * BB];
        const float* ur = &Us[k * CC];
        s0 += hv * ur[0]; s1 += hv * ur[1]; s2 += hv * ur[2];
        s3 += hv * ur[3]; s4 += hv * ur[4];
    }

    float m = fmaxf(fmaxf(fmaxf(s0, s1), fmaxf(s2, s3)), s4);
    float sum = __expf(s0 - m) + __expf(s1 - m) + __expf(s2 - m)
              + __expf(s3 - m) + __expf(s4 - m);
    float lse = m + __logf(sum);
    int lab = labels[b * TT + t];
    float lc = (lab == 0) ? s0 : (lab == 1) ? s1 : (lab == 2) ? s2
             : (lab == 3) ? s3 : s4;
    float ce = lse - lc;
    int mk;
    if (g_mask_is_byte) mk = (((const unsigned char*)maskp)[b * TT + t] != 0);
    else                mk = (((const int*)maskp)[b * TT + t] != 0);

    sd[tid] = mk ? (double)ce : 0.0;
    sc[tid] = mk;
    __syncthreads();
    for (int off = CE_TB / 2; off; off >>= 1) {
        if (tid < off) { sd[tid] += sd[tid + off]; sc[tid] += sc[tid + off]; }
        __syncthreads();
    }
    if (tid == 0) { g_bsum[blockIdx.x] = sd[0]; g_bcnt[blockIdx.x] = sc[0]; }
}

__global__ void fin_k(float* out) {
    __shared__ double sd[256];
    __shared__ int    sc[256];
    int i = threadIdx.x;
    double s = 0.0; int c = 0;
    for (int j = i; j < CE_BLOCKS; j += 256) { s += g_bsum[j]; c += g_bcnt[j]; }
    sd[i] = s; sc[i] = c;
    __syncthreads();
    for (int off = 128; off; off >>= 1) {
        if (i < off) { sd[i] += sd[i + off]; sc[i] += sc[i + off]; }
        __syncthreads();
    }
    if (i == 0) out[0] = (float)(sd[0] / (double)sc[0]);
}

// ----------------- launcher -----------------
extern "C" void kernel_launch(void* const* d_in, const int* in_sizes, int n_in,
                              void* d_out, int out_size)
{
    const int*   tokens = (const int*)d_in[0];
    const int*   labels = (const int*)d_in[1];
    const void*  mask   = d_in[2];
    const float* emb    = (const float*)d_in[3];
    const float* Wx     = (const float*)d_in[4];
    const float* Wh     = (const float*)d_in[5];
    const float* bias   = (const float*)d_in[6];
    const float* U      = (const float*)d_in[7];
    const float* b2     = (const float*)d_in[8];
    float* out = (float*)d_out;

    initdetect_k<<<(HH * BB + 255) / 256, 256>>>((const unsigned int*)mask);
    wpad_k<<<(KPAD * NZP + 255) / 256, 256>>>(Wx, Wh, bias);
    gather_k<<<dim3(TT, BB / 64), 256>>>(tokens, emb);

    dim3 ggrid(BB / GM, NZP / GN);                 // (8, 17) = 136 blocks
    for (int t = 0; t < TT; ++t) {
        lstm_step_k<<<ggrid, 256>>>(t);            // t=0 is launch #3 (profiled)
    }

    ce_k<<<CE_BLOCKS, CE_TB>>>(U, b2, labels, mask);
    fin_k<<<1, 256>>>(out);
    (void)in_sizes; (void)n_in; (void)out_size;
}